// round 12
// baseline (speedup 1.0000x reference)
#include <cuda_runtime.h>
#include <cuda_bf16.h>
#include <cstdint>
#include <cstddef>

#define BB 4
#define SS 2048
#define EE 1024
#define DD 64
#define HH 16

// ---------------- scratch (static __device__ globals: allocation-free) -------------
__device__ __align__(16) uint32_t g_Qh[BB * SS * 32];       // Q bf16x2-hi, pairs along d
__device__ __align__(16) uint32_t g_Ql[BB * SS * 32];
__device__ __align__(16) uint32_t g_Kh[BB * SS * 32];
__device__ __align__(16) uint32_t g_Kl[BB * SS * 32];
__device__ __align__(16) float    g_V[BB * SS * DD];        // fp32
__device__ __align__(16) uint32_t g_Wth[192 * 512];         // W^T bf16x2-hi [n=192][k-pairs]
__device__ __align__(16) uint32_t g_Wtl[192 * 512];
__device__ __align__(16) float    g_E[(size_t)BB * SS * SS];// exp(S), tf32-pre-rounded (64 MB)
__device__ __align__(16) float    g_Zpart[BB * 16 * SS];
__device__ __align__(16) float    g_Opart[BB * 8 * SS * DD];

// ---------------- helpers ----------------------------------------------------------
__device__ __forceinline__ float tf32rna(float a) {
    uint32_t r;
    asm("cvt.rna.tf32.f32 %0, %1;" : "=r"(r) : "f"(a));
    return __uint_as_float(r);
}

__device__ __forceinline__ void split2(float a, float b, uint32_t& hi, uint32_t& lo) {
    __nv_bfloat162 H, L;
    H.x = __float2bfloat16_rn(a);
    H.y = __float2bfloat16_rn(b);
    L.x = __float2bfloat16_rn(a - __bfloat162float(H.x));
    L.y = __float2bfloat16_rn(b - __bfloat162float(H.y));
    hi = *(uint32_t*)&H;
    lo = *(uint32_t*)&L;
}

__device__ __forceinline__ void mma_bf16(float* c, const uint32_t* a, const uint32_t* b) {
    asm volatile(
        "mma.sync.aligned.m16n8k16.row.col.f32.bf16.bf16.f32 "
        "{%0,%1,%2,%3}, {%4,%5,%6,%7}, {%8,%9}, {%0,%1,%2,%3};"
        : "+f"(c[0]), "+f"(c[1]), "+f"(c[2]), "+f"(c[3])
        : "r"(a[0]), "r"(a[1]), "r"(a[2]), "r"(a[3]), "r"(b[0]), "r"(b[1]));
}

__device__ __forceinline__ void mma168(float* c, const uint32_t* a, const uint32_t* b) {
    asm volatile(
        "mma.sync.aligned.m16n8k8.row.col.f32.tf32.tf32.f32 "
        "{%0,%1,%2,%3}, {%4,%5,%6,%7}, {%8,%9}, {%0,%1,%2,%3};"
        : "+f"(c[0]), "+f"(c[1]), "+f"(c[2]), "+f"(c[3])
        : "r"(a[0]), "r"(a[1]), "r"(a[2]), "r"(a[3]), "r"(b[0]), "r"(b[1]));
}

#define PITCH 68    // fp32 smem pitch
#define UPITCH 36   // u32 (bf16x2) smem pitch

// =====================================================================================
// Kernel 0: pre-split W^T into bf16 hi/lo [n=192][k-pairs=512].
// =====================================================================================
__global__ void wsplit_kernel(const float* __restrict__ Wq,
                              const float* __restrict__ Wk,
                              const float* __restrict__ Wv) {
    int n = blockIdx.x;
    int z = n >> 6, d = n & 63;
    const float* __restrict__ W = (z == 0) ? Wq : (z == 1) ? Wk : Wv;
    for (int k2 = threadIdx.x; k2 < 512; k2 += 256) {
        float a = W[(size_t)(2 * k2) * DD + d];
        float b = W[(size_t)(2 * k2 + 1) * DD + d];
        uint32_t hi, lo;
        split2(a, b, hi, lo);
        g_Wth[n * 512 + k2] = hi;
        g_Wtl[n * 512 + k2] = lo;
    }
}

// =====================================================================================
// Kernel 1 (projmma): grid (128 mtiles, 3 z), 128 threads (4 warps 2x2).
// M=64, N=64, K=1024 via bf16x2 3-term mma.sync.
// Epilogue: z=0/1 -> Q/K stored PRE-SPLIT bf16 hi/lo; z=2 -> V fp32.
// =====================================================================================
__global__ __launch_bounds__(128) void projmma_kernel(const float* __restrict__ x) {
    __shared__ uint32_t smu[4 * 64 * UPITCH];
    uint32_t* Xh = smu;
    uint32_t* Xl = Xh + 64 * UPITCH;
    uint32_t* Wh = Xl + 64 * UPITCH;
    uint32_t* Wl = Wh + 64 * UPITCH;

    const int z  = blockIdx.y;
    const int m0 = blockIdx.x * 64;
    const int tid = threadIdx.x, lane = tid & 31, warp = tid >> 5;
    const int wi = warp >> 1, wj = warp & 1;
    const int g = lane >> 2, c = lane & 3;

    float C[2][4][4] = {};

    for (int k0 = 0; k0 < EE; k0 += 64) {
        for (int idx = tid; idx < 1024; idx += 128) {
            int r = idx >> 4, c4 = (idx & 15) << 2;
            float4 v = *(const float4*)(x + (size_t)(m0 + r) * EE + k0 + c4);
            uint32_t h0, l0, h1, l1;
            split2(v.x, v.y, h0, l0);
            split2(v.z, v.w, h1, l1);
            int base = r * UPITCH + (c4 >> 1);
            Xh[base] = h0; Xh[base + 1] = h1;
            Xl[base] = l0; Xl[base + 1] = l1;
        }
        for (int idx = tid; idx < 512; idx += 128) {
            int r = idx >> 3, c16 = (idx & 7) << 2;
            size_t off = (size_t)(z * 64 + r) * 512 + (k0 >> 1) + c16;
            *(uint4*)(Wh + r * UPITCH + c16) = *(const uint4*)(g_Wth + off);
            *(uint4*)(Wl + r * UPITCH + c16) = *(const uint4*)(g_Wtl + off);
        }
        __syncthreads();

        #pragma unroll
        for (int t3 = 0; t3 < 3; t3++) {
            const uint32_t* A = (t3 == 2) ? Xl : Xh;
            const uint32_t* B = (t3 == 1) ? Wl : Wh;
            #pragma unroll
            for (int ks = 0; ks < 4; ks++) {
                int kb = ks * 8;
                uint32_t a[2][4], bb[4][2];
                #pragma unroll
                for (int mt = 0; mt < 2; mt++) {
                    int row = wi * 32 + mt * 16 + g;
                    a[mt][0] = A[row * UPITCH + kb + c];
                    a[mt][1] = A[(row + 8) * UPITCH + kb + c];
                    a[mt][2] = A[row * UPITCH + kb + c + 4];
                    a[mt][3] = A[(row + 8) * UPITCH + kb + c + 4];
                }
                #pragma unroll
                for (int nt = 0; nt < 4; nt++) {
                    int n = wj * 32 + nt * 8 + g;
                    bb[nt][0] = B[n * UPITCH + kb + c];
                    bb[nt][1] = B[n * UPITCH + kb + c + 4];
                }
                #pragma unroll
                for (int mt = 0; mt < 2; mt++)
                    #pragma unroll
                    for (int nt = 0; nt < 4; nt++)
                        mma_bf16(C[mt][nt], a[mt], bb[nt]);
            }
        }
        __syncthreads();
    }

    if (z == 2) {
        #pragma unroll
        for (int mt = 0; mt < 2; mt++) {
            int m = m0 + wi * 32 + mt * 16 + g;
            int b = m >> 11, s = m & 2047;
            #pragma unroll
            for (int nt = 0; nt < 4; nt++) {
                int d = wj * 32 + nt * 8 + 2 * c;
                *(float2*)(g_V + ((size_t)(b * SS + s)) * DD + d) =
                    make_float2(C[mt][nt][0], C[mt][nt][1]);
                *(float2*)(g_V + ((size_t)(b * SS + s + 8)) * DD + d) =
                    make_float2(C[mt][nt][2], C[mt][nt][3]);
            }
        }
    } else {
        uint32_t* __restrict__ dh = z ? g_Kh : g_Qh;
        uint32_t* __restrict__ dl = z ? g_Kl : g_Ql;
        #pragma unroll
        for (int mt = 0; mt < 2; mt++) {
            int m = m0 + wi * 32 + mt * 16 + g;
            int b = m >> 11, s = m & 2047;
            #pragma unroll
            for (int nt = 0; nt < 4; nt++) {
                int pr = wj * 16 + nt * 4 + c;
                uint32_t h, l;
                split2(C[mt][nt][0], C[mt][nt][1], h, l);
                dh[(size_t)(b * SS + s) * 32 + pr] = h;
                dl[(size_t)(b * SS + s) * 32 + pr] = l;
                split2(C[mt][nt][2], C[mt][nt][3], h, l);
                dh[(size_t)(b * SS + s + 8) * 32 + pr] = h;
                dl[(size_t)(b * SS + s + 8) * 32 + pr] = l;
            }
        }
    }
}

// =====================================================================================
// Kernel 2 (score): 128x128 S-tile via bf16x2 3-term mma.sync; pure uint4 tile loads.
// exp -> store E (tf32-pre-rounded, streaming stores) + column partial sums.
// grid (16 i, 16 j, 4 b), 256 threads (8 warps 4x2).
// =====================================================================================
#define SC_SMEM (4 * 128 * UPITCH * 4 + 256 * 17 * 4)   // 91136

__global__ __launch_bounds__(256) void score_kernel() {
    extern __shared__ uint32_t smu[];
    uint32_t* Qh = smu;
    uint32_t* Ql = Qh + 128 * UPITCH;
    uint32_t* Kh = Ql + 128 * UPITCH;
    uint32_t* Kl = Kh + 128 * UPITCH;
    float* red = (float*)(Kl + 128 * UPITCH);

    const int tid = threadIdx.x, lane = tid & 31, warp = tid >> 5;
    const int wi = warp >> 1, wj = warp & 1;
    const int g = lane >> 2, c = lane & 3;
    const int b = blockIdx.z, i0 = blockIdx.x * 128, j0 = blockIdx.y * 128;

    for (int idx = tid; idx < 1024; idx += 256) {
        int r = idx >> 3, cq = (idx & 7) << 2;
        int base = r * UPITCH + cq;
        *(uint4*)(Qh + base) = *(const uint4*)(g_Qh + (size_t)(b * SS + i0 + r) * 32 + cq);
        *(uint4*)(Ql + base) = *(const uint4*)(g_Ql + (size_t)(b * SS + i0 + r) * 32 + cq);
        *(uint4*)(Kh + base) = *(const uint4*)(g_Kh + (size_t)(b * SS + j0 + r) * 32 + cq);
        *(uint4*)(Kl + base) = *(const uint4*)(g_Kl + (size_t)(b * SS + j0 + r) * 32 + cq);
    }
    __syncthreads();

    float C[2][8][4] = {};

    #pragma unroll
    for (int t3 = 0; t3 < 3; t3++) {
        const uint32_t* A = (t3 == 2) ? Ql : Qh;
        const uint32_t* B = (t3 == 1) ? Kl : Kh;
        #pragma unroll
        for (int ks = 0; ks < 4; ks++) {
            int kb = ks * 8;
            uint32_t a[2][4], bf[8][2];
            #pragma unroll
            for (int mt = 0; mt < 2; mt++) {
                int row = wi * 32 + mt * 16 + g;
                a[mt][0] = A[row * UPITCH + kb + c];
                a[mt][1] = A[(row + 8) * UPITCH + kb + c];
                a[mt][2] = A[row * UPITCH + kb + c + 4];
                a[mt][3] = A[(row + 8) * UPITCH + kb + c + 4];
            }
            #pragma unroll
            for (int nt = 0; nt < 8; nt++) {
                int jr = wj * 64 + nt * 8 + g;
                bf[nt][0] = B[jr * UPITCH + kb + c];
                bf[nt][1] = B[jr * UPITCH + kb + c + 4];
            }
            #pragma unroll
            for (int mt = 0; mt < 2; mt++)
                #pragma unroll
                for (int nt = 0; nt < 8; nt++)
                    mma_bf16(C[mt][nt], a[mt], bf[nt]);
        }
    }

    float part[16];
    #pragma unroll
    for (int p = 0; p < 16; p++) part[p] = 0.f;

    #pragma unroll
    for (int mt = 0; mt < 2; mt++) {
        #pragma unroll
        for (int nt = 0; nt < 8; nt++) {
            float e0 = __expf(C[mt][nt][0]);
            float e1 = __expf(C[mt][nt][1]);
            float e2 = __expf(C[mt][nt][2]);
            float e3 = __expf(C[mt][nt][3]);
            int ig = i0 + wi * 32 + mt * 16 + g;
            int jg = j0 + wj * 64 + nt * 8 + 2 * c;
            __stcs((float2*)(g_E + ((size_t)b * SS + ig) * SS + jg),
                   make_float2(tf32rna(e0), tf32rna(e1)));
            __stcs((float2*)(g_E + ((size_t)b * SS + ig + 8) * SS + jg),
                   make_float2(tf32rna(e2), tf32rna(e3)));
            part[nt * 2 + 0] += e0 + e2;
            part[nt * 2 + 1] += e1 + e3;
        }
    }
    #pragma unroll
    for (int p = 0; p < 16; p++) red[tid * 17 + p] = part[p];
    __syncthreads();

    if (tid < 128) {
        int t_wj = tid >> 6, jl = tid & 63;
        int nt = jl >> 3, cc = (jl & 7) >> 1, par = jl & 1;
        int p = nt * 2 + par;
        float s = 0.f;
        #pragma unroll
        for (int twi = 0; twi < 4; twi++)
            #pragma unroll
            for (int q = 0; q < 8; q++)
                s += red[((twi * 2 + t_wj) * 32 + q * 4 + cc) * 17 + p];
        g_Zpart[((size_t)(b * 16 + blockIdx.x)) * SS + j0 + tid] = s;
    }
}

// =====================================================================================
// Kernel 3 (out, vscale FUSED): partial out = (E·zinv)[i, k-chunk] @ V^T.
// zinv computed in prologue from Zpart; E scaled+rounded at smem load; V loaded raw
// [k][d] and read TRANSPOSED for B fragments. grid (16 i, 8 ksplit, 4 b), 256 thr.
// =====================================================================================
#define OU_SMEM (128 * PITCH * 4 + 64 * PITCH * 4 + 256 * 4)   // 34816+17408+1024 = 53248

__global__ __launch_bounds__(256) void out_kernel() {
    extern __shared__ float sm[];
    float* Et = sm;                        // [i][k] pitch 68, pre-scaled by zinv, tf32
    float* Vs = sm + 128 * PITCH;          // [k][d] pitch 68, tf32
    float* zi = Vs + 64 * PITCH;           // [256] zinv for this ks chunk

    const int tid = threadIdx.x, lane = tid & 31, warp = tid >> 5;
    const int wi = warp >> 1, wj = warp & 1;
    const int g = lane >> 2, c = lane & 3;
    const int b = blockIdx.z, i0 = blockIdx.x * 128, ks_id = blockIdx.y;

    // prologue: zinv for k in [ks_id*256, ks_id*256+256)
    {
        int k = ks_id * 256 + tid;
        float s = 0.f;
        #pragma unroll
        for (int p = 0; p < 16; p++) s += g_Zpart[((size_t)(b * 16 + p)) * SS + k];
        zi[tid] = 1.0f / s;
    }
    __syncthreads();

    float C[2][4][4] = {};

    for (int kc = 0; kc < 4; kc++) {
        const int kcg = ks_id * 4 + kc;
        const int k0 = kcg * 64;
        // E tile: streaming load, scale by zinv (per column k), rna round
        for (int idx = tid; idx < 2048; idx += 256) {
            int r = idx >> 4, c4 = (idx & 15) << 2;
            float4 v = __ldcs((const float4*)(g_E + ((size_t)(b * SS + i0 + r)) * SS + k0 + c4));
            int zb = kc * 64 + c4;
            v.x = tf32rna(v.x * zi[zb + 0]);
            v.y = tf32rna(v.y * zi[zb + 1]);
            v.z = tf32rna(v.z * zi[zb + 2]);
            v.w = tf32rna(v.w * zi[zb + 3]);
            *(float4*)(Et + r * PITCH + c4) = v;
        }
        // V tile: raw [k][d], rna round
        for (int idx = tid; idx < 1024; idx += 256) {
            int r = idx >> 4, c4 = (idx & 15) << 2;
            float4 v = *(const float4*)(g_V + ((size_t)(b * SS + k0 + r)) * DD + c4);
            v.x = tf32rna(v.x); v.y = tf32rna(v.y);
            v.z = tf32rna(v.z); v.w = tf32rna(v.w);
            *(float4*)(Vs + r * PITCH + c4) = v;
        }
        __syncthreads();

        #pragma unroll
        for (int ks = 0; ks < 8; ks++) {
            const int kk = ks * 8;
            uint32_t a[2][4], bf[4][2];
            #pragma unroll
            for (int mt = 0; mt < 2; mt++) {
                int row = wi * 32 + mt * 16 + g;
                a[mt][0] = __float_as_uint(Et[row * PITCH + kk + c]);
                a[mt][1] = __float_as_uint(Et[(row + 8) * PITCH + kk + c]);
                a[mt][2] = __float_as_uint(Et[row * PITCH + kk + c + 4]);
                a[mt][3] = __float_as_uint(Et[(row + 8) * PITCH + kk + c + 4]);
            }
            #pragma unroll
            for (int nt = 0; nt < 4; nt++) {
                int dr = wj * 32 + nt * 8 + g;
                // B[n=dr][k] = Vs[k][dr]  (transposed read)
                bf[nt][0] = __float_as_uint(Vs[(kk + c) * PITCH + dr]);
                bf[nt][1] = __float_as_uint(Vs[(kk + c + 4) * PITCH + dr]);
            }
            #pragma unroll
            for (int mt = 0; mt < 2; mt++)
                #pragma unroll
                for (int nt = 0; nt < 4; nt++)
                    mma168(C[mt][nt], a[mt], bf[nt]);
        }
        __syncthreads();
    }

    #pragma unroll
    for (int mt = 0; mt < 2; mt++) {
        #pragma unroll
        for (int nt = 0; nt < 4; nt++) {
            int ig = i0 + wi * 32 + mt * 16 + g;
            int dg = wj * 32 + nt * 8 + 2 * c;
            size_t base = ((size_t)((b * 8 + ks_id) * SS + ig)) * DD + dg;
            *(float2*)(g_Opart + base) = make_float2(C[mt][nt][0], C[mt][nt][1]);
            *(float2*)(g_Opart + base + 8 * DD) = make_float2(C[mt][nt][2], C[mt][nt][3]);
        }
    }
}

// =====================================================================================
// Kernel 4: reduce 8 k-split partials, write 16 tiled head copies (streaming).
// =====================================================================================
__global__ void finalize_kernel(float* __restrict__ out) {
    int gI = blockIdx.x * 256 + threadIdx.x;
    int c4 = (gI & 15) << 2;
    int i  = (gI >> 4) & 2047;
    int b  = gI >> 15;
    float4 s = make_float4(0.f, 0.f, 0.f, 0.f);
    #pragma unroll
    for (int sp = 0; sp < 8; sp++) {
        float4 p = __ldcs((const float4*)(g_Opart +
                          ((size_t)((b * 8 + sp) * SS + i)) * DD + c4));
        s.x += p.x; s.y += p.y; s.z += p.z; s.w += p.w;
    }
    float* base = out + ((size_t)(b * SS + i)) * (HH * DD) + c4;
    #pragma unroll
    for (int h = 0; h < HH; h++) __stcs((float4*)(base + h * DD), s);
}

// =====================================================================================
extern "C" void kernel_launch(void* const* d_in, const int* in_sizes, int n_in,
                              void* d_out, int out_size) {
    const float* x  = (const float*)d_in[0];
    const float* Wq = (const float*)d_in[1];
    const float* Wk = (const float*)d_in[2];
    const float* Wv = (const float*)d_in[3];
    float* out = (float*)d_out;

    cudaFuncSetAttribute(score_kernel, cudaFuncAttributeMaxDynamicSharedMemorySize, SC_SMEM);
    cudaFuncSetAttribute(out_kernel,   cudaFuncAttributeMaxDynamicSharedMemorySize, OU_SMEM);

    wsplit_kernel<<<192, 256>>>(Wq, Wk, Wv);
    projmma_kernel<<<dim3(128, 3), 128>>>(x);
    score_kernel<<<dim3(16, 16, BB), 256, SC_SMEM>>>();
    out_kernel<<<dim3(16, 8, BB), 256, OU_SMEM>>>();
    finalize_kernel<<<(BB * SS * HH) / 256, 256>>>(out);
}

// round 13
// speedup vs baseline: 1.1067x; 1.1067x over previous
#include <cuda_runtime.h>
#include <cuda_bf16.h>
#include <cstdint>
#include <cstddef>

#define BB 4
#define SS 2048
#define EE 1024
#define DD 64
#define HH 16

// ---------------- scratch (static __device__ globals: allocation-free) -------------
__device__ __align__(16) uint32_t g_Qh[BB * SS * 32];       // Q bf16x2-hi, pairs along d
__device__ __align__(16) uint32_t g_Ql[BB * SS * 32];
__device__ __align__(16) uint32_t g_Kh[BB * SS * 32];
__device__ __align__(16) uint32_t g_Kl[BB * SS * 32];
__device__ __align__(16) float    g_V[BB * SS * DD];        // fp32
__device__ __align__(16) uint32_t g_Wth[192 * 512];         // W^T bf16x2-hi [n=192][k-pairs]
__device__ __align__(16) uint32_t g_Wtl[192 * 512];
__device__ __align__(16) float    g_E[(size_t)BB * SS * SS];// exp(S), tf32-pre-rounded (64 MB)
__device__ __align__(16) float    g_Wvt[BB * 32 * 64 * 64]; // (V^T/Z) tf32, BLOCKED [b][kc][d][kin]
__device__ __align__(16) float    g_Zpart[BB * 16 * SS];
__device__ __align__(16) float    g_Opart[BB * 8 * SS * DD];

// ---------------- helpers ----------------------------------------------------------
__device__ __forceinline__ float tf32rna(float a) {
    uint32_t r;
    asm("cvt.rna.tf32.f32 %0, %1;" : "=r"(r) : "f"(a));
    return __uint_as_float(r);
}

__device__ __forceinline__ void split2(float a, float b, uint32_t& hi, uint32_t& lo) {
    __nv_bfloat162 H, L;
    H.x = __float2bfloat16_rn(a);
    H.y = __float2bfloat16_rn(b);
    L.x = __float2bfloat16_rn(a - __bfloat162float(H.x));
    L.y = __float2bfloat16_rn(b - __bfloat162float(H.y));
    hi = *(uint32_t*)&H;
    lo = *(uint32_t*)&L;
}

__device__ __forceinline__ void mma_bf16(float* c, const uint32_t* a, const uint32_t* b) {
    asm volatile(
        "mma.sync.aligned.m16n8k16.row.col.f32.bf16.bf16.f32 "
        "{%0,%1,%2,%3}, {%4,%5,%6,%7}, {%8,%9}, {%0,%1,%2,%3};"
        : "+f"(c[0]), "+f"(c[1]), "+f"(c[2]), "+f"(c[3])
        : "r"(a[0]), "r"(a[1]), "r"(a[2]), "r"(a[3]), "r"(b[0]), "r"(b[1]));
}

__device__ __forceinline__ void mma168(float* c, const uint32_t* a, const uint32_t* b) {
    asm volatile(
        "mma.sync.aligned.m16n8k8.row.col.f32.tf32.tf32.f32 "
        "{%0,%1,%2,%3}, {%4,%5,%6,%7}, {%8,%9}, {%0,%1,%2,%3};"
        : "+f"(c[0]), "+f"(c[1]), "+f"(c[2]), "+f"(c[3])
        : "r"(a[0]), "r"(a[1]), "r"(a[2]), "r"(a[3]), "r"(b[0]), "r"(b[1]));
}

#define PITCH 68    // fp32 smem pitch
#define UPITCH 36   // u32 (bf16x2) smem pitch

// fp32 tile load, default cache policy
__device__ __forceinline__ void ldt(float* dst, const float* __restrict__ src,
                                    int rows, int pitch_f) {
    for (int idx = threadIdx.x; idx < rows * 16; idx += 256) {
        int r = idx >> 4, c4 = (idx & 15) << 2;
        float4 v = *(const float4*)(src + (size_t)r * pitch_f + c4);
        *(float4*)(dst + r * PITCH + c4) = v;
    }
}
// fp32 tile load, streaming (evict-first) — for read-once E
__device__ __forceinline__ void ldt_cs(float* dst, const float* __restrict__ src,
                                       int rows, int pitch_f) {
    for (int idx = threadIdx.x; idx < rows * 16; idx += 256) {
        int r = idx >> 4, c4 = (idx & 15) << 2;
        float4 v = __ldcs((const float4*)(src + (size_t)r * pitch_f + c4));
        *(float4*)(dst + r * PITCH + c4) = v;
    }
}

// =====================================================================================
// Kernel 0: pre-split W^T into bf16 hi/lo [n=192][k-pairs=512].
// =====================================================================================
__global__ void wsplit_kernel(const float* __restrict__ Wq,
                              const float* __restrict__ Wk,
                              const float* __restrict__ Wv) {
    int n = blockIdx.x;
    int z = n >> 6, d = n & 63;
    const float* __restrict__ W = (z == 0) ? Wq : (z == 1) ? Wk : Wv;
    for (int k2 = threadIdx.x; k2 < 512; k2 += 256) {
        float a = W[(size_t)(2 * k2) * DD + d];
        float b = W[(size_t)(2 * k2 + 1) * DD + d];
        uint32_t hi, lo;
        split2(a, b, hi, lo);
        g_Wth[n * 512 + k2] = hi;
        g_Wtl[n * 512 + k2] = lo;
    }
}

// =====================================================================================
// Kernel 1 (projmma, WIDE): grid (64 mtiles, 3 z), 256 threads (8 warps 4x2).
// M=128, N=64, K=1024 via bf16x2 3-term mma.sync. 2 warps/SMSP for latency hiding.
// Epilogue: z=0/1 -> Q/K stored PRE-SPLIT bf16 hi/lo; z=2 -> V fp32.
// =====================================================================================
#define PJ_SMEM ((2 * 128 + 2 * 64) * UPITCH * 4)   // Xh,Xl(128) + Wh,Wl(64) = 55296 B

__global__ __launch_bounds__(256) void projmma_kernel(const float* __restrict__ x) {
    extern __shared__ uint32_t smu[];
    uint32_t* Xh = smu;
    uint32_t* Xl = Xh + 128 * UPITCH;
    uint32_t* Wh = Xl + 128 * UPITCH;
    uint32_t* Wl = Wh + 64 * UPITCH;

    const int z  = blockIdx.y;
    const int m0 = blockIdx.x * 128;
    const int tid = threadIdx.x, lane = tid & 31, warp = tid >> 5;
    const int wi = warp >> 1, wj = warp & 1;
    const int g = lane >> 2, c = lane & 3;

    float C[2][4][4] = {};

    for (int k0 = 0; k0 < EE; k0 += 64) {
        // x tile 128x64: load fp32, split, pack
        for (int idx = tid; idx < 2048; idx += 256) {
            int r = idx >> 4, c4 = (idx & 15) << 2;
            float4 v = *(const float4*)(x + (size_t)(m0 + r) * EE + k0 + c4);
            uint32_t h0, l0, h1, l1;
            split2(v.x, v.y, h0, l0);
            split2(v.z, v.w, h1, l1);
            int base = r * UPITCH + (c4 >> 1);
            Xh[base] = h0; Xh[base + 1] = h1;
            Xl[base] = l0; Xl[base + 1] = l1;
        }
        // W^T tile 64x64 (pre-split): uint4 copies
        for (int idx = tid; idx < 512; idx += 256) {
            int r = idx >> 3, c16 = (idx & 7) << 2;
            size_t off = (size_t)(z * 64 + r) * 512 + (k0 >> 1) + c16;
            *(uint4*)(Wh + r * UPITCH + c16) = *(const uint4*)(g_Wth + off);
            *(uint4*)(Wl + r * UPITCH + c16) = *(const uint4*)(g_Wtl + off);
        }
        __syncthreads();

        #pragma unroll
        for (int t3 = 0; t3 < 3; t3++) {
            const uint32_t* A = (t3 == 2) ? Xl : Xh;
            const uint32_t* B = (t3 == 1) ? Wl : Wh;
            #pragma unroll
            for (int ks = 0; ks < 4; ks++) {
                int kb = ks * 8;
                uint32_t a[2][4], bb[4][2];
                #pragma unroll
                for (int mt = 0; mt < 2; mt++) {
                    int row = wi * 32 + mt * 16 + g;
                    a[mt][0] = A[row * UPITCH + kb + c];
                    a[mt][1] = A[(row + 8) * UPITCH + kb + c];
                    a[mt][2] = A[row * UPITCH + kb + c + 4];
                    a[mt][3] = A[(row + 8) * UPITCH + kb + c + 4];
                }
                #pragma unroll
                for (int nt = 0; nt < 4; nt++) {
                    int n = wj * 32 + nt * 8 + g;
                    bb[nt][0] = B[n * UPITCH + kb + c];
                    bb[nt][1] = B[n * UPITCH + kb + c + 4];
                }
                #pragma unroll
                for (int mt = 0; mt < 2; mt++)
                    #pragma unroll
                    for (int nt = 0; nt < 4; nt++)
                        mma_bf16(C[mt][nt], a[mt], bb[nt]);
            }
        }
        __syncthreads();
    }

    if (z == 2) {
        #pragma unroll
        for (int mt = 0; mt < 2; mt++) {
            int m = m0 + wi * 32 + mt * 16 + g;
            int b = m >> 11, s = m & 2047;
            #pragma unroll
            for (int nt = 0; nt < 4; nt++) {
                int d = wj * 32 + nt * 8 + 2 * c;
                *(float2*)(g_V + ((size_t)(b * SS + s)) * DD + d) =
                    make_float2(C[mt][nt][0], C[mt][nt][1]);
                *(float2*)(g_V + ((size_t)(b * SS + s + 8)) * DD + d) =
                    make_float2(C[mt][nt][2], C[mt][nt][3]);
            }
        }
    } else {
        uint32_t* __restrict__ dh = z ? g_Kh : g_Qh;
        uint32_t* __restrict__ dl = z ? g_Kl : g_Ql;
        #pragma unroll
        for (int mt = 0; mt < 2; mt++) {
            int m = m0 + wi * 32 + mt * 16 + g;
            int b = m >> 11, s = m & 2047;
            #pragma unroll
            for (int nt = 0; nt < 4; nt++) {
                int pr = wj * 16 + nt * 4 + c;
                uint32_t h, l;
                split2(C[mt][nt][0], C[mt][nt][1], h, l);
                dh[(size_t)(b * SS + s) * 32 + pr] = h;
                dl[(size_t)(b * SS + s) * 32 + pr] = l;
                split2(C[mt][nt][2], C[mt][nt][3], h, l);
                dh[(size_t)(b * SS + s + 8) * 32 + pr] = h;
                dl[(size_t)(b * SS + s + 8) * 32 + pr] = l;
            }
        }
    }
}

// =====================================================================================
// Kernel 2 (score): 128x128 S-tile via bf16x2 3-term mma.sync; pure uint4 tile loads.
// exp -> store E (tf32-pre-rounded, streaming stores) + column partial sums.
// grid (16 i, 16 j, 4 b), 256 threads (8 warps 4x2).
// =====================================================================================
#define SC_SMEM (4 * 128 * UPITCH * 4 + 256 * 17 * 4)   // 91136

__global__ __launch_bounds__(256) void score_kernel() {
    extern __shared__ uint32_t smu[];
    uint32_t* Qh = smu;
    uint32_t* Ql = Qh + 128 * UPITCH;
    uint32_t* Kh = Ql + 128 * UPITCH;
    uint32_t* Kl = Kh + 128 * UPITCH;
    float* red = (float*)(Kl + 128 * UPITCH);

    const int tid = threadIdx.x, lane = tid & 31, warp = tid >> 5;
    const int wi = warp >> 1, wj = warp & 1;
    const int g = lane >> 2, c = lane & 3;
    const int b = blockIdx.z, i0 = blockIdx.x * 128, j0 = blockIdx.y * 128;

    for (int idx = tid; idx < 1024; idx += 256) {
        int r = idx >> 3, cq = (idx & 7) << 2;
        int base = r * UPITCH + cq;
        *(uint4*)(Qh + base) = *(const uint4*)(g_Qh + (size_t)(b * SS + i0 + r) * 32 + cq);
        *(uint4*)(Ql + base) = *(const uint4*)(g_Ql + (size_t)(b * SS + i0 + r) * 32 + cq);
        *(uint4*)(Kh + base) = *(const uint4*)(g_Kh + (size_t)(b * SS + j0 + r) * 32 + cq);
        *(uint4*)(Kl + base) = *(const uint4*)(g_Kl + (size_t)(b * SS + j0 + r) * 32 + cq);
    }
    __syncthreads();

    float C[2][8][4] = {};

    #pragma unroll
    for (int t3 = 0; t3 < 3; t3++) {
        const uint32_t* A = (t3 == 2) ? Ql : Qh;
        const uint32_t* B = (t3 == 1) ? Kl : Kh;
        #pragma unroll
        for (int ks = 0; ks < 4; ks++) {
            int kb = ks * 8;
            uint32_t a[2][4], bf[8][2];
            #pragma unroll
            for (int mt = 0; mt < 2; mt++) {
                int row = wi * 32 + mt * 16 + g;
                a[mt][0] = A[row * UPITCH + kb + c];
                a[mt][1] = A[(row + 8) * UPITCH + kb + c];
                a[mt][2] = A[row * UPITCH + kb + c + 4];
                a[mt][3] = A[(row + 8) * UPITCH + kb + c + 4];
            }
            #pragma unroll
            for (int nt = 0; nt < 8; nt++) {
                int jr = wj * 64 + nt * 8 + g;
                bf[nt][0] = B[jr * UPITCH + kb + c];
                bf[nt][1] = B[jr * UPITCH + kb + c + 4];
            }
            #pragma unroll
            for (int mt = 0; mt < 2; mt++)
                #pragma unroll
                for (int nt = 0; nt < 8; nt++)
                    mma_bf16(C[mt][nt], a[mt], bf[nt]);
        }
    }

    float part[16];
    #pragma unroll
    for (int p = 0; p < 16; p++) part[p] = 0.f;

    #pragma unroll
    for (int mt = 0; mt < 2; mt++) {
        #pragma unroll
        for (int nt = 0; nt < 8; nt++) {
            float e0 = __expf(C[mt][nt][0]);
            float e1 = __expf(C[mt][nt][1]);
            float e2 = __expf(C[mt][nt][2]);
            float e3 = __expf(C[mt][nt][3]);
            int ig = i0 + wi * 32 + mt * 16 + g;
            int jg = j0 + wj * 64 + nt * 8 + 2 * c;
            __stcs((float2*)(g_E + ((size_t)b * SS + ig) * SS + jg),
                   make_float2(tf32rna(e0), tf32rna(e1)));
            __stcs((float2*)(g_E + ((size_t)b * SS + ig + 8) * SS + jg),
                   make_float2(tf32rna(e2), tf32rna(e3)));
            part[nt * 2 + 0] += e0 + e2;
            part[nt * 2 + 1] += e1 + e3;
        }
    }
    #pragma unroll
    for (int p = 0; p < 16; p++) red[tid * 17 + p] = part[p];
    __syncthreads();

    if (tid < 128) {
        int t_wj = tid >> 6, jl = tid & 63;
        int nt = jl >> 3, cc = (jl & 7) >> 1, par = jl & 1;
        int p = nt * 2 + par;
        float s = 0.f;
        #pragma unroll
        for (int twi = 0; twi < 4; twi++)
            #pragma unroll
            for (int q = 0; q < 8; q++)
                s += red[((twi * 2 + t_wj) * 32 + q * 4 + cc) * 17 + p];
        g_Zpart[((size_t)(b * 16 + blockIdx.x)) * SS + j0 + tid] = s;
    }
}

// =====================================================================================
// Kernel 3 (vscale, zinv fused): Z from 16 partials;
// Wvt BLOCKED [b][kc][d][64] = tf32(V[k][d]/Z[k]); contiguous 16KB block writes.
// grid (32 kc, 4 b), 256 threads.
// =====================================================================================
__global__ __launch_bounds__(256) void vscale_kernel() {
    __shared__ float vs[64][65];
    __shared__ float sz[64];
    const int b = blockIdx.y, kc = blockIdx.x, k0 = kc * 64, t = threadIdx.x;
    if (t < 64) {
        float s = 0.f;
        #pragma unroll
        for (int p = 0; p < 16; p++) s += g_Zpart[((size_t)(b * 16 + p)) * SS + k0 + t];
        sz[t] = 1.0f / s;
    }
    __syncthreads();
    for (int idx = t; idx < 1024; idx += 256) {
        int r = idx >> 4, c4 = (idx & 15) << 2;
        float zi = sz[r];
        float4 v = *(const float4*)(g_V + ((size_t)(b * SS + k0 + r)) * DD + c4);
        vs[r][c4 + 0] = v.x * zi; vs[r][c4 + 1] = v.y * zi;
        vs[r][c4 + 2] = v.z * zi; vs[r][c4 + 3] = v.w * zi;
    }
    __syncthreads();
    for (int idx = t; idx < 1024; idx += 256) {
        int d = idx >> 4, c4 = (idx & 15) << 2;
        float4 o;
        o.x = tf32rna(vs[c4 + 0][d]);
        o.y = tf32rna(vs[c4 + 1][d]);
        o.z = tf32rna(vs[c4 + 2][d]);
        o.w = tf32rna(vs[c4 + 3][d]);
        *(float4*)(g_Wvt + ((size_t)((b * 32 + kc) * 64 + d)) * 64 + c4) = o;
    }
}

// =====================================================================================
// Kernel 4 (out, R11 form): partial out = E[i, k-chunk] @ Wvt^T, single tf32 mma.sync.
// E loads streaming; W loads contiguous blocked. grid (16 i, 8 ksplit, 4 b), 256 thr.
// =====================================================================================
#define OU_SMEM (128 * PITCH * 4 + 64 * PITCH * 4)    // 52224

__global__ __launch_bounds__(256) void out_kernel() {
    extern __shared__ float sm[];
    float* Et = sm;
    float* Wt = sm + 128 * PITCH;

    const int tid = threadIdx.x, lane = tid & 31, warp = tid >> 5;
    const int wi = warp >> 1, wj = warp & 1;
    const int g = lane >> 2, c = lane & 3;
    const int b = blockIdx.z, i0 = blockIdx.x * 128, ks_id = blockIdx.y;

    float C[2][4][4] = {};

    for (int kc = 0; kc < 4; kc++) {
        const int kcg = ks_id * 4 + kc;       // global 64-chunk index
        const int k0 = kcg * 64;
        ldt_cs(Et, g_E + ((size_t)b * SS + i0) * SS + k0, 128, SS);
        ldt(Wt, g_Wvt + ((size_t)(b * 32 + kcg)) * 64 * 64, 64, 64);
        __syncthreads();

        #pragma unroll
        for (int ks = 0; ks < 8; ks++) {
            const int kk = ks * 8;
            uint32_t a[2][4], bf[4][2];
            #pragma unroll
            for (int mt = 0; mt < 2; mt++) {
                int row = wi * 32 + mt * 16 + g;
                a[mt][0] = __float_as_uint(Et[row * PITCH + kk + c]);
                a[mt][1] = __float_as_uint(Et[(row + 8) * PITCH + kk + c]);
                a[mt][2] = __float_as_uint(Et[row * PITCH + kk + c + 4]);
                a[mt][3] = __float_as_uint(Et[(row + 8) * PITCH + kk + c + 4]);
            }
            #pragma unroll
            for (int nt = 0; nt < 4; nt++) {
                int dr = wj * 32 + nt * 8 + g;
                bf[nt][0] = __float_as_uint(Wt[dr * PITCH + kk + c]);
                bf[nt][1] = __float_as_uint(Wt[dr * PITCH + kk + c + 4]);
            }
            #pragma unroll
            for (int mt = 0; mt < 2; mt++)
                #pragma unroll
                for (int nt = 0; nt < 4; nt++)
                    mma168(C[mt][nt], a[mt], bf[nt]);
        }
        __syncthreads();
    }

    #pragma unroll
    for (int mt = 0; mt < 2; mt++) {
        #pragma unroll
        for (int nt = 0; nt < 4; nt++) {
            int ig = i0 + wi * 32 + mt * 16 + g;
            int dg = wj * 32 + nt * 8 + 2 * c;
            size_t base = ((size_t)((b * 8 + ks_id) * SS + ig)) * DD + dg;
            *(float2*)(g_Opart + base) = make_float2(C[mt][nt][0], C[mt][nt][1]);
            *(float2*)(g_Opart + base + 8 * DD) = make_float2(C[mt][nt][2], C[mt][nt][3]);
        }
    }
}

// =====================================================================================
// Kernel 5: reduce 8 k-split partials, write 16 tiled head copies (streaming).
// =====================================================================================
__global__ void finalize_kernel(float* __restrict__ out) {
    int gI = blockIdx.x * 256 + threadIdx.x;
    int c4 = (gI & 15) << 2;
    int i  = (gI >> 4) & 2047;
    int b  = gI >> 15;
    float4 s = make_float4(0.f, 0.f, 0.f, 0.f);
    #pragma unroll
    for (int sp = 0; sp < 8; sp++) {
        float4 p = __ldcs((const float4*)(g_Opart +
                          ((size_t)((b * 8 + sp) * SS + i)) * DD + c4));
        s.x += p.x; s.y += p.y; s.z += p.z; s.w += p.w;
    }
    float* base = out + ((size_t)(b * SS + i)) * (HH * DD) + c4;
    #pragma unroll
    for (int h = 0; h < HH; h++) __stcs((float4*)(base + h * DD), s);
}

// =====================================================================================
extern "C" void kernel_launch(void* const* d_in, const int* in_sizes, int n_in,
                              void* d_out, int out_size) {
    const float* x  = (const float*)d_in[0];
    const float* Wq = (const float*)d_in[1];
    const float* Wk = (const float*)d_in[2];
    const float* Wv = (const float*)d_in[3];
    float* out = (float*)d_out;

    cudaFuncSetAttribute(projmma_kernel, cudaFuncAttributeMaxDynamicSharedMemorySize, PJ_SMEM);
    cudaFuncSetAttribute(score_kernel,   cudaFuncAttributeMaxDynamicSharedMemorySize, SC_SMEM);
    cudaFuncSetAttribute(out_kernel,     cudaFuncAttributeMaxDynamicSharedMemorySize, OU_SMEM);

    wsplit_kernel<<<192, 256>>>(Wq, Wk, Wv);
    projmma_kernel<<<dim3(64, 3), 256, PJ_SMEM>>>(x);
    score_kernel<<<dim3(16, 16, BB), 256, SC_SMEM>>>();
    vscale_kernel<<<dim3(32, BB), 256>>>();
    out_kernel<<<dim3(16, 8, BB), 256, OU_SMEM>>>();
    finalize_kernel<<<(BB * SS * HH) / 256, 256>>>(out);
}